// round 7
// baseline (speedup 1.0000x reference)
#include <cuda_runtime.h>
#include <cooperative_groups.h>
#include <math.h>

namespace cg = cooperative_groups;

#define EPS 1e-8f
typedef unsigned long long u64;
// B=64, S=64, I=64, O=64, N=1024, M=64, H=256, 4H=1024, P=268
// 4-CTA cluster handles 2 batches. Ranks {0,1} own batch A's memory n-halves,
// {2,3} batch B's. GEMMs cluster-wide for BOTH batches via packed f32x2 math.
// Round 7: split arrive/wait cluster barriers with shadow work, fused Wx|Wh,
// contiguous vh banks, norm pre-pass, atomic-free phase-7 reduction.

__device__ float g_W[384 * 1024];   // rows 0..127 = Wx, 128..383 = Wh

struct SMem {
    float  mem[64 * 512];     // own batch's memory half, [m][nl] (128 KB)
    float4 part[2048];        // GEMM / addressing partials (32 KB), reused
    float  wr[512], ww[512];
    float  t1[512], t2[512];
    float2 vh[768];           // bank0: [0,64)x [64,128)r [128,384)h ; bank1: +384
    float2 h2c[256];          // current-step h pairs {hA, hB}
    float  nnp[1024];         // memory-norm partials (pre-pass)
    float  c[2][64];          // [batch][own 64 dims]
    float  gates[2][256];     // own col slice per batch
    float  p[272];            // full head output for OWN batch
    float2 krw[64];           // {kr[m], kw[m]}
    float  e[64], a[64];
    float  rrecv[4][64];
    float2 rvec2[64];         // {rA, rB}
    float  scal[16];          // 0..5 read head, 6=|kr|, 7=|kw|, 8..13 write head
    float  qhalo[4];
    float  wh_r[2], wh_w[2];
    float  xch[4];
    float2 red[32];
};

__device__ __forceinline__ float sigmoidf_(float x) { return 1.f / (1.f + expf(-x)); }
__device__ __forceinline__ float softplusf_(float x) { return fmaxf(x, 0.f) + log1pf(expf(-fabsf(x))); }

__device__ __forceinline__ u64 pk2(float a, float b) {
    u64 r; asm("mov.b64 %0, {%1, %2};" : "=l"(r) : "f"(a), "f"(b)); return r;
}
__device__ __forceinline__ float2 up2(u64 v) {
    float2 r; asm("mov.b64 {%0, %1}, %2;" : "=f"(r.x), "=f"(r.y) : "l"(v)); return r;
}
__device__ __forceinline__ void fma2(u64& d, u64 a, u64 b) {
    asm("fma.rn.f32x2 %0, %1, %2, %0;" : "+l"(d) : "l"(a), "l"(b));
}
__device__ __forceinline__ u64 fma2n(u64 a, u64 b, u64 c) {
    u64 d; asm("fma.rn.f32x2 %0, %1, %2, %3;" : "=l"(d) : "l"(a), "l"(b), "l"(c)); return d;
}
__device__ __forceinline__ u64 mul2(u64 a, u64 b) {
    u64 d; asm("mul.rn.f32x2 %0, %1, %2;" : "=l"(d) : "l"(a), "l"(b)); return d;
}
__device__ __forceinline__ u64 add2(u64 a, u64 b) {
    u64 d; asm("add.rn.f32x2 %0, %1, %2;" : "=l"(d) : "l"(a), "l"(b)); return d;
}
#define CL_ARRIVE() asm volatile("barrier.cluster.arrive.aligned;" ::: "memory")
#define CL_WAIT()   asm volatile("barrier.cluster.wait.aligned;"   ::: "memory")

__device__ __forceinline__ float2 blockReduceSum2(float2 v, float2* red) {
#pragma unroll
    for (int o = 16; o; o >>= 1) {
        v.x += __shfl_xor_sync(0xffffffffu, v.x, o);
        v.y += __shfl_xor_sync(0xffffffffu, v.y, o);
    }
    int w = threadIdx.x >> 5;
    if ((threadIdx.x & 31) == 0) red[w] = v;
    __syncthreads();
    if (threadIdx.x < 32) {
        v = red[threadIdx.x];
#pragma unroll
        for (int o = 16; o; o >>= 1) {
            v.x += __shfl_xor_sync(0xffffffffu, v.x, o);
            v.y += __shfl_xor_sync(0xffffffffu, v.y, o);
        }
        if (threadIdx.x == 0) red[0] = v;
    }
    __syncthreads();
    v = red[0];
    __syncthreads();
    return v;
}

__global__ void __launch_bounds__(1024, 1) __cluster_dims__(4, 1, 1)
ntm_kernel(const float* __restrict__ x,       // (64,64,64)
           const float* __restrict__ b_lstm,  // (1024)
           const float* __restrict__ W_head,  // (256,268)
           const float* __restrict__ b_head,  // (268)
           const float* __restrict__ W_out,   // (320,64)
           const float* __restrict__ b_out,   // (64)
           float* __restrict__ out)           // (64,64,64)
{
    extern __shared__ char smraw[];
    SMem* s = (SMem*)smraw;
    cg::cluster_group cl = cg::this_cluster();

    const int rank = (int)cl.block_rank();    // 0..3
    const int clid = blockIdx.x >> 2;
    const int t    = threadIdx.x;

    SMem* P0 = (SMem*)cl.map_shared_rank(smraw, 0);
    SMem* P1 = (SMem*)cl.map_shared_rank(smraw, 1);
    SMem* P2 = (SMem*)cl.map_shared_rank(smraw, 2);
    SMem* P3 = (SMem*)cl.map_shared_rank(smraw, 3);
    SMem* PP[4] = {P0, P1, P2, P3};
    SMem* pp = (SMem*)cl.map_shared_rank(smraw, rank ^ 1);   // pair peer

    float*      partf = (float*)s->part;
    float2*     part2 = (float2*)s->part;
    ulonglong2* partq = (ulonglong2*)s->part;
    float4*     mem4  = (float4*)s->mem;
    ulonglong2* memq  = (ulonglong2*)s->mem;

    const int bgA = clid * 2, bgB = clid * 2 + 1;

    // Hoisted out-GEMM constants (same thread roles every step)
    const int jc8 = t & 15, ch8 = t >> 4;          // 8a/8b thread roles
    const int col8 = rank * 16 + jc8;
    float4 w8a;
    {
        int r0 = ch8 * 4;
        w8a = make_float4(W_out[(r0 + 0) * 64 + col8], W_out[(r0 + 1) * 64 + col8],
                          W_out[(r0 + 2) * 64 + col8], W_out[(r0 + 3) * 64 + col8]);
    }
    const float w8b = W_out[(256 + (t >> 4)) * 64 + col8];
    const float bo  = (t < 16) ? b_out[rank * 16 + t] : 0.f;

    // ---- init ----
    {
        float4 iv = make_float4(0.01f, 0.01f, 0.01f, 0.01f);
#pragma unroll
        for (int i = 0; i < 8; ++i) mem4[i * 1024 + t] = iv;
        if (t < 512) { float w0 = ((rank & 1) == 0 && t == 0) ? 1.f : 0.f; s->wr[t] = w0; s->ww[t] = w0; }
        if (t < 768) s->vh[t] = make_float2(0.f, 0.f);
        if (t < 256) s->h2c[t] = make_float2(0.f, 0.f);
        if (t < 128) ((float*)s->c)[t] = 0.f;
        if (t < 64)  s->rvec2[t] = make_float2(0.f, 0.f);
        if (t < 64) {   // initial x for step 0, both banks
            float2 xv = make_float2(x[(bgA << 6) * 64 + t], x[(bgB << 6) * 64 + t]);
            s->vh[t] = xv; s->vh[384 + t] = xv;
        }
        if (t == 0) {
            float hv = (rank & 1) ? 1.f : 0.f;
            s->wh_r[0] = hv; s->wh_w[0] = hv;
            s->wh_r[1] = 0.f; s->wh_w[1] = 0.f;
        }
    }
    cl.sync();

    float2 xpref = make_float2(0.f, 0.f);

    for (int step = 0; step < 64; ++step) {
        const int prv = step & 1, cur = prv ^ 1;

        // ---- phase 2: gates, own 256 cols x 2 batches, fused W, contiguous vh ----
        {
            int qi = t & 63, qb = qi >> 4, qw = qi & 15;
            int col4 = qb * 64 + rank * 16 + qw;
            int ch = t >> 6;                 // 0..15, rows [24ch, 24ch+24)
            const ulonglong2* gw2 = (const ulonglong2*)g_W;
            const float2* vrow = s->vh + prv * 384;
            u64 aA01 = 0ull, aA23 = 0ull, aB01 = 0ull, aB23 = 0ull;
            int r0 = ch * 24;
#pragma unroll 8
            for (int rr = r0; rr < r0 + 24; ++rr) {
                ulonglong2 w2 = gw2[rr * 256 + col4];
                float2 vv = vrow[rr];
                u64 vA2 = pk2(vv.x, vv.x), vB2 = pk2(vv.y, vv.y);
                fma2(aA01, w2.x, vA2); fma2(aA23, w2.y, vA2);
                fma2(aB01, w2.x, vB2); fma2(aB23, w2.y, vB2);
            }
            ulonglong2 sa; sa.x = aA01; sa.y = aA23;
            ulonglong2 sb; sb.x = aB01; sb.y = aB23;
            partq[t] = sa;
            partq[1024 + t] = sb;
        }
        __syncthreads();
        if (t < 128) {
            int bat = t >> 6, qi = t & 63;
            int qb = qi >> 4, qw = qi & 15;
            int col4 = qb * 64 + rank * 16 + qw;
            ulonglong2 bb = ((const ulonglong2*)b_lstm)[col4];
            u64 a01 = bb.x, a23 = bb.y;
#pragma unroll
            for (int ch = 0; ch < 16; ++ch) {
                ulonglong2 pc = partq[bat * 1024 + ch * 64 + qi];
                a01 = add2(a01, pc.x); a23 = add2(a23, pc.y);
            }
            ulonglong2 g; g.x = a01; g.y = a23;
            ((ulonglong2*)s->gates[bat])[qi] = g;
        }
        __syncthreads();

        // ---- phase 3: LSTM pointwise; publish h pairs to all 4 CTAs ----
        if (t < 128) {
            int bat = t >> 6, jl = t & 63;
            float ig = s->gates[bat][jl],       fg = s->gates[bat][64 + jl],
                  gg = s->gates[bat][128 + jl], og = s->gates[bat][192 + jl];
            float cc = sigmoidf_(fg) * s->c[bat][jl] + sigmoidf_(ig) * tanhf(gg);
            s->c[bat][jl] = cc;
            float hv = sigmoidf_(og) * tanhf(cc);
            int gj = rank * 64 + jl;
#pragma unroll
            for (int i = 0; i < 4; ++i) {
                ((float*)&PP[i]->vh[128 + cur * 384 + gj])[bat] = hv;
                ((float*)&PP[i]->h2c[gj])[bat] = hv;
            }
        }
        CL_ARRIVE();   // S1 arrive
        // ---- S1 shadow: memory-norm pre-pass, first half ----
        {
            int nl0 = t & 511, m0 = (t >> 9) * 32;
            float nn = 0.f;
#pragma unroll 8
            for (int m = m0; m < m0 + 16; ++m) { float v = s->mem[m * 512 + nl0]; nn += v * v; }
            s->nnp[t] = nn;
        }
        CL_WAIT();     // S1: full new h pairs in all 4 CTAs

        // ---- phase 4: head GEMM, own 68 cols x both batches packed ----
        const int cr = (rank < 3) ? 68 : 64;
        if (t < 952) {
            int ch = t / 68, j = t - ch * 68;       // ch 0..13
            u64 acc = 0ull;
            if (j < cr) {
                int col = 68 * rank + j;
                int k0 = (ch * 128) / 7, k1 = ((ch + 1) * 128) / 7;
                for (int k = k0; k < k1; ++k) {
                    float w = W_head[k * 268 + col];
                    u64 hv = *(const u64*)(s->h2c + k);
                    fma2(acc, hv, pk2(w, w));
                }
            }
            part2[t] = up2(acc);
        }
        __syncthreads();
        if (t < 68 && t < cr) {
            int col = 68 * rank + t;
            float2 acc = make_float2(0.f, 0.f);
#pragma unroll
            for (int ch = 0; ch < 14; ++ch) {
                float2 pv = part2[ch * 68 + t];
                acc.x += pv.x; acc.y += pv.y;
            }
            float bh = b_head[col];
            acc.x += bh; acc.y += bh;
            P0->p[col] = acc.x; P1->p[col] = acc.x;
            P2->p[col] = acc.y; P3->p[col] = acc.y;
        }
        CL_ARRIVE();   // S2 arrive
        // ---- S2 shadow: memory-norm pre-pass, second half ----
        {
            int nl0 = t & 511, m0 = (t >> 9) * 32;
            float nn = s->nnp[t];
#pragma unroll 8
            for (int m = m0 + 16; m < m0 + 32; ++m) { float v = s->mem[m * 512 + nl0]; nn += v * v; }
            s->nnp[t] = nn;
        }
        CL_WAIT();     // S2: full p for own batch in each CTA

        // ---- phase 5: parse heads ----
        if (t < 64) s->krw[t].x = tanhf(s->p[t]);
        else if (t < 128) s->krw[t - 64].y = tanhf(s->p[70 + t - 64]);
        else if (t < 192) s->e[t - 128] = sigmoidf_(s->p[140 + (t - 128)]);
        else if (t < 256) s->a[t - 192] = s->p[204 + (t - 192)];
        else if (t == 256) {
            s->scal[0] = softplusf_(s->p[64]);
            s->scal[1] = sigmoidf_(s->p[65]);
            float a0 = s->p[66], a1 = s->p[67], a2 = s->p[68];
            float mx = fmaxf(a0, fmaxf(a1, a2));
            float e0 = expf(a0 - mx), e1 = expf(a1 - mx), e2 = expf(a2 - mx);
            float sm = e0 + e1 + e2;
            s->scal[2] = e0 / sm; s->scal[3] = e1 / sm; s->scal[4] = e2 / sm;
            s->scal[5] = 1.f + softplusf_(s->p[69]);
        } else if (t == 288) {
            s->scal[8] = softplusf_(s->p[134]);
            s->scal[9] = sigmoidf_(s->p[135]);
            float a0 = s->p[136], a1 = s->p[137], a2 = s->p[138];
            float mx = fmaxf(a0, fmaxf(a1, a2));
            float e0 = expf(a0 - mx), e1 = expf(a1 - mx), e2 = expf(a2 - mx);
            float sm = e0 + e1 + e2;
            s->scal[10] = e0 / sm; s->scal[11] = e1 / sm; s->scal[12] = e2 / sm;
            s->scal[13] = 1.f + softplusf_(s->p[139]);
        }
        __syncthreads();
        if (t < 32) {
            float kv = s->krw[t].x, kv2 = s->krw[t + 32].x;
            float v = kv * kv + kv2 * kv2;
#pragma unroll
            for (int o = 16; o; o >>= 1) v += __shfl_xor_sync(0xffffffffu, v, o);
            if (t == 0) s->scal[6] = sqrtf(v);
        } else if (t < 64) {
            int l = t - 32;
            float kv = s->krw[l].y, kv2 = s->krw[l + 32].y;
            float v = kv * kv + kv2 * kv2;
#pragma unroll
            for (int o = 16; o; o >>= 1) v += __shfl_xor_sync(0xffffffffu, v, o);
            if (l == 0) s->scal[7] = sqrtf(v);
        }
        __syncthreads();

        // ---- phase 6: addressing dots over own 512 n-rows, packed {dr,dw} ----
        const int nl = t & 511, mh = t >> 9;
        {
            u64 drw = 0ull;
            int m0 = mh * 32;
#pragma unroll 8
            for (int m = m0; m < m0 + 32; ++m) {
                float v = s->mem[m * 512 + nl];
                u64 kv = *(const u64*)(s->krw + m);
                fma2(drw, kv, pk2(v, v));
            }
            float2 d = up2(drw);
            s->part[t] = make_float4(d.x, d.y, 0.f, 0.f);
        }
        __syncthreads();
        const bool lead = (t < 512);
        float qr = 0.f, qw = 0.f, er = 0.f, ew = 0.f;
        if (lead) {
            float4 p0 = s->part[t], p1 = s->part[t + 512];
            float dr = p0.x + p1.x, dw = p0.y + p1.y;
            float nn = s->nnp[nl] + s->nnp[nl + 512];
            float nrm = sqrtf(nn);
            qr = s->scal[0] * (dr / (s->scal[6] * nrm + EPS));
            qw = s->scal[8] * (dw / (s->scal[7] * nrm + EPS));
            if (nl == 0)   { pp->qhalo[0] = qr; pp->qhalo[2] = qw; }
            if (nl == 511) { pp->qhalo[1] = qr; pp->qhalo[3] = qw; }
            er = expf(qr);          // |q| <= beta (softplus-bounded): overflow-safe
            ew = expf(qw);
        }
        float2 lsum = blockReduceSum2(make_float2(er, ew), s->red);
        if (t == 0) { pp->xch[0] = lsum.x; pp->xch[1] = lsum.y; }
        CL_ARRIVE();   // S3 arrive
        // ---- S3 shadow: out-GEMM h-part (8a), weights resident ----
        {
            const float* hb = (const float*)s->h2c;
            int r0 = ch8 * 4;     // rows r0..r0+3, batch pairs interleaved
            u64 acc = 0ull;
            u64 h0 = *(const u64*)(hb + 2 * (r0 + 0));
            u64 h1 = *(const u64*)(hb + 2 * (r0 + 1));
            u64 h2 = *(const u64*)(hb + 2 * (r0 + 2));
            u64 h3 = *(const u64*)(hb + 2 * (r0 + 3));
            fma2(acc, h0, pk2(w8a.x, w8a.x));
            fma2(acc, h1, pk2(w8a.y, w8a.y));
            fma2(acc, h2, pk2(w8a.z, w8a.z));
            fma2(acc, h3, pk2(w8a.w, w8a.w));
            part2[t] = up2(acc);
        }
        CL_WAIT();     // S3: exp-sums + boundary q exchanged within pair
        const float gsr = lsum.x + s->xch[0];
        const float gsw = lsum.y + s->xch[1];
        const float g_r = s->scal[1], g_w = s->scal[9];
        if (lead) {
            float wgr = g_r * (er / gsr) + (1.f - g_r) * s->wr[nl];
            float wgw = g_w * (ew / gsw) + (1.f - g_w) * s->ww[nl];
            s->t1[nl] = wgr;
            s->t2[nl] = wgw;
        }
        __syncthreads();
        float wpr = 0.f, wpw = 0.f;
        if (lead) {
            float t1p = (nl == 511) ? (g_r * (expf(s->qhalo[0]) / gsr) + (1.f - g_r) * s->wh_r[0]) : s->t1[nl + 1];
            float t1m = (nl == 0)   ? (g_r * (expf(s->qhalo[1]) / gsr) + (1.f - g_r) * s->wh_r[1]) : s->t1[nl - 1];
            float t2p = (nl == 511) ? (g_w * (expf(s->qhalo[2]) / gsw) + (1.f - g_w) * s->wh_w[0]) : s->t2[nl + 1];
            float t2m = (nl == 0)   ? (g_w * (expf(s->qhalo[3]) / gsw) + (1.f - g_w) * s->wh_w[1]) : s->t2[nl - 1];
            float wsr = s->scal[2]  * t1p + s->scal[3]  * s->t1[nl] + s->scal[4]  * t1m;
            float wsw = s->scal[10] * t2p + s->scal[11] * s->t2[nl] + s->scal[12] * t2m;
            wpr = (wsr > 0.f) ? expf(s->scal[5]  * logf(wsr)) : 0.f;
            wpw = (wsw > 0.f) ? expf(s->scal[13] * logf(wsw)) : 0.f;
        }
        float2 lsp = blockReduceSum2(make_float2(wpr, wpw), s->red);
        if (t == 0) { pp->xch[2] = lsp.x; pp->xch[3] = lsp.y; }
        CL_ARRIVE();   // S4 arrive
        CL_WAIT();     // S4: sharpen sums exchanged within pair
        if (lead) {
            float wrv = wpr / ((lsp.x + s->xch[2]) + EPS);
            float wwv = wpw / ((lsp.y + s->xch[3]) + EPS);
            s->wr[nl] = wrv;
            s->ww[nl] = wwv;
            if (nl == 0)   { pp->wh_r[0] = wrv; pp->wh_w[0] = wwv; }   // ordered by S5
            if (nl == 511) { pp->wh_r[1] = wrv; pp->wh_w[1] = wwv; }
        }
        __syncthreads();

        // ---- phase 7: fused read (old mem) + erase/add update, packed, atomic-free ----
        {
            int n4 = t & 127, mch = t >> 7;
            int wid = t >> 5;
            ulonglong2 wr2 = ((const ulonglong2*)s->wr)[n4];
            ulonglong2 ww2 = ((const ulonglong2*)s->ww)[n4];
            const u64 one2 = pk2(1.f, 1.f);
#pragma unroll 4
            for (int mi = 0; mi < 8; ++mi) {
                int m = mch * 8 + mi;
                float em = s->e[m], am = s->a[m];
                u64 nem2 = pk2(-em, -em), am2 = pk2(am, am);
                ulonglong2 v2 = memq[m * 128 + n4];
                u64 rp2 = 0ull;
                fma2(rp2, wr2.x, v2.x); fma2(rp2, wr2.y, v2.y);
                float2 rr = up2(rp2);
                float rp = rr.x + rr.y;
                u64 f01 = fma2n(ww2.x, nem2, one2);
                u64 f23 = fma2n(ww2.y, nem2, one2);
                u64 g01 = mul2(ww2.x, am2);
                u64 g23 = mul2(ww2.y, am2);
                v2.x = fma2n(v2.x, f01, g01);
                v2.y = fma2n(v2.y, f23, g23);
                memq[m * 128 + n4] = v2;
#pragma unroll
                for (int o = 16; o; o >>= 1) rp += __shfl_xor_sync(0xffffffffu, rp, o);
                if ((t & 31) == 0) partf[4096 + wid * 8 + mi] = rp;
            }
        }
        __syncthreads();
        if (t < 64) {   // sum 4 warp-partials per m, broadcast to all 4 CTAs
            int grp = t >> 3, mi = t & 7;
            float v = partf[4096 + (grp * 4 + 0) * 8 + mi]
                    + partf[4096 + (grp * 4 + 1) * 8 + mi]
                    + partf[4096 + (grp * 4 + 2) * 8 + mi]
                    + partf[4096 + (grp * 4 + 3) * 8 + mi];
#pragma unroll
            for (int i = 0; i < 4; ++i) PP[i]->rrecv[rank][t] = v;
        }
        CL_ARRIVE();   // S5 arrive
        // ---- S5 shadow: prefetch next-step x ----
        if (t < 64) {
            int sn = (step < 63) ? step + 1 : 63;
            xpref = make_float2(x[((bgA << 6) + sn) * 64 + t],
                                x[((bgB << 6) + sn) * 64 + t]);
        }
        CL_WAIT();     // S5: r partials everywhere (+ w halos ordered)
        if (t < 64) {
            float2 rv = make_float2(s->rrecv[0][t] + s->rrecv[1][t],
                                    s->rrecv[2][t] + s->rrecv[3][t]);
            s->rvec2[t] = rv;
            s->vh[64 + t] = rv;  s->vh[448 + t] = rv;   // r into both banks
            s->vh[t] = xpref;    s->vh[384 + t] = xpref; // next x into both banks
        }
        __syncthreads();

        // ---- phase 8b: add r-part (resident weight), reduce, write out ----
        {
            float2 rv = s->rvec2[ch8];
            float2 pv = part2[t];
            pv.x += rv.x * w8b; pv.y += rv.y * w8b;
            part2[t] = pv;
        }
        __syncthreads();
        if (t < 128) {
            int jc = t & 15, g = t >> 4;       // 8 groups of 8 chunks
            float2 acc = make_float2(0.f, 0.f);
#pragma unroll
            for (int k = 0; k < 8; ++k) {
                float2 pv = part2[(g * 8 + k) * 16 + jc];
                acc.x += pv.x; acc.y += pv.y;
            }
            part2[1024 + t] = acc;
        }
        __syncthreads();
        if (t < 16) {
            float2 acc = make_float2(bo, bo);
#pragma unroll
            for (int g = 0; g < 8; ++g) {
                float2 pv = part2[1024 + g * 16 + t];
                acc.x += pv.x; acc.y += pv.y;
            }
            int col = rank * 16 + t;
            out[((bgA << 6) + step) * 64 + col] = acc.x;
            out[((bgB << 6) + step) * 64 + col] = acc.y;
        }
        __syncthreads();
    }
}

extern "C" void kernel_launch(void* const* d_in, const int* in_sizes, int n_in,
                              void* d_out, int out_size) {
    const float* x      = (const float*)d_in[0];
    const float* Wx     = (const float*)d_in[1];
    const float* Wh     = (const float*)d_in[2];
    const float* b_lstm = (const float*)d_in[3];
    const float* W_head = (const float*)d_in[4];
    const float* b_head = (const float*)d_in[5];
    const float* W_out  = (const float*)d_in[6];
    const float* b_out  = (const float*)d_in[7];
    float* out = (float*)d_out;

    // Fuse Wx|Wh into one contiguous __device__ buffer (async D2D, graph-capturable)
    cudaMemcpyToSymbolAsync(g_W, Wx, 128 * 1024 * sizeof(float), 0,
                            cudaMemcpyDeviceToDevice, 0);
    cudaMemcpyToSymbolAsync(g_W, Wh, 256 * 1024 * sizeof(float),
                            128 * 1024 * sizeof(float), cudaMemcpyDeviceToDevice, 0);

    size_t smem = sizeof(SMem);
    cudaFuncSetAttribute(ntm_kernel, cudaFuncAttributeMaxDynamicSharedMemorySize, (int)smem);
    ntm_kernel<<<128, 1024, smem>>>(x, b_lstm, W_head, b_head, W_out, b_out, out);
}

// round 8
// speedup vs baseline: 1.0797x; 1.0797x over previous
#include <cuda_runtime.h>
#include <cooperative_groups.h>
#include <math.h>

namespace cg = cooperative_groups;

#define EPS 1e-8f
typedef unsigned long long u64;
// B=64, S=64, I=64, O=64, N=1024, M=64, H=256, 4H=1024, P=268
// 4-CTA cluster, 2 batches. Ranks {0,1}: batch A memory halves; {2,3}: batch B.
// Round 8: 3 cluster syncs/step. S1 = h broadcast + head-partial reduce (head GEMM
// uses own h quarter pre-sync; mem update+norm fused in S1 shadow). S3 = softmax
// sums + q halos (out-GEMM h-part in shadow). S45 = sharpen sums + r partials +
// boundary wp (normalization deferred; r divided by Z post-sync).

__device__ float g_W[384 * 1024];   // rows 0..127 = Wx, 128..383 = Wh

struct SMem {
    float  mem[64 * 512];     // own batch's memory half, [m][nl] (128 KB)
    float4 part[2048];        // scratch partials (32 KB), region-multiplexed
    float  wr[512], ww[512];  // unnormalized wp mid-step, normalized post-S45
    float  t1[512], t2[512];
    float2 vh[768];           // bank0: [0,64)x [64,128)r [128,384)h ; bank1: +384
    float2 h2c[256];          // current-step full h pairs {hA, hB}
    float2 h2own[64];         // own h quarter pairs
    float  nnp[512];          // per-n norm (own half)
    float  c[2][64];
    float  gates[2][256];
    float  p[272];            // full head output for OWN batch
    float  ppart[4][272];     // head partials from 4 ranks
    float2 krw[64];           // {kr[m], kw[m]}
    float  e[64], a[64];
    float  rrecv[4][64];
    float2 rvec2[64];
    float  scal[16];
    float  qhalo[4];
    float  wh_r[2], wh_w[2];  // normalized prev-w halos
    float  whp_r[2], whp_w[2];// unnormalized boundary wp from peer
    float  xch[4];            // pair softmax-sum slots
    float2 zrecv[4];          // sharpen sums from all 4 ranks
    float2 red[32];
};

__device__ __forceinline__ float sigmoidf_(float x) { return 1.f / (1.f + expf(-x)); }
__device__ __forceinline__ float softplusf_(float x) { return fmaxf(x, 0.f) + log1pf(expf(-fabsf(x))); }

__device__ __forceinline__ u64 pk2(float a, float b) {
    u64 r; asm("mov.b64 %0, {%1, %2};" : "=l"(r) : "f"(a), "f"(b)); return r;
}
__device__ __forceinline__ float2 up2(u64 v) {
    float2 r; asm("mov.b64 {%0, %1}, %2;" : "=f"(r.x), "=f"(r.y) : "l"(v)); return r;
}
__device__ __forceinline__ void fma2(u64& d, u64 a, u64 b) {
    asm("fma.rn.f32x2 %0, %1, %2, %0;" : "+l"(d) : "l"(a), "l"(b));
}
__device__ __forceinline__ u64 fma2n(u64 a, u64 b, u64 c) {
    u64 d; asm("fma.rn.f32x2 %0, %1, %2, %3;" : "=l"(d) : "l"(a), "l"(b), "l"(c)); return d;
}
__device__ __forceinline__ u64 mul2(u64 a, u64 b) {
    u64 d; asm("mul.rn.f32x2 %0, %1, %2;" : "=l"(d) : "l"(a), "l"(b)); return d;
}
__device__ __forceinline__ u64 add2(u64 a, u64 b) {
    u64 d; asm("add.rn.f32x2 %0, %1, %2;" : "=l"(d) : "l"(a), "l"(b)); return d;
}
#define CL_ARRIVE() asm volatile("barrier.cluster.arrive.aligned;" ::: "memory")
#define CL_WAIT()   asm volatile("barrier.cluster.wait.aligned;"   ::: "memory")

// Single-barrier block sum of a float2 across 1024 threads; result in all threads.
__device__ __forceinline__ float2 blockReduceSum2(float2 v, float2* red) {
#pragma unroll
    for (int o = 16; o; o >>= 1) {
        v.x += __shfl_xor_sync(0xffffffffu, v.x, o);
        v.y += __shfl_xor_sync(0xffffffffu, v.y, o);
    }
    if ((threadIdx.x & 31) == 0) red[threadIdx.x >> 5] = v;
    __syncthreads();
    float2 w = red[threadIdx.x & 31];
#pragma unroll
    for (int o = 16; o; o >>= 1) {
        w.x += __shfl_xor_sync(0xffffffffu, w.x, o);
        w.y += __shfl_xor_sync(0xffffffffu, w.y, o);
    }
    return w;
}

__global__ void __launch_bounds__(1024, 1) __cluster_dims__(4, 1, 1)
ntm_kernel(const float* __restrict__ x,       // (64,64,64)
           const float* __restrict__ b_lstm,  // (1024)
           const float* __restrict__ W_head,  // (256,268)
           const float* __restrict__ b_head,  // (268)
           const float* __restrict__ W_out,   // (320,64)
           const float* __restrict__ b_out,   // (64)
           float* __restrict__ out)           // (64,64,64)
{
    extern __shared__ char smraw[];
    SMem* s = (SMem*)smraw;
    cg::cluster_group cl = cg::this_cluster();

    const int rank = (int)cl.block_rank();
    const int clid = blockIdx.x >> 2;
    const int t    = threadIdx.x;

    SMem* P0 = (SMem*)cl.map_shared_rank(smraw, 0);
    SMem* P1 = (SMem*)cl.map_shared_rank(smraw, 1);
    SMem* P2 = (SMem*)cl.map_shared_rank(smraw, 2);
    SMem* P3 = (SMem*)cl.map_shared_rank(smraw, 3);
    SMem* PP[4] = {P0, P1, P2, P3};
    SMem* pp = (SMem*)cl.map_shared_rank(smraw, rank ^ 1);   // pair peer

    float*      partf = (float*)s->part;
    float2*     part2 = (float2*)s->part;
    ulonglong2* partq = (ulonglong2*)s->part;
    float4*     mem4  = (float4*)s->mem;
    ulonglong2* memq  = (ulonglong2*)s->mem;

    const int bgA = clid * 2, bgB = clid * 2 + 1;

    // Hoisted out-GEMM constants
    const int jc8 = t & 15, ch8 = t >> 4;
    const int col8 = rank * 16 + jc8;
    float4 w8a;
    {
        int r0 = ch8 * 4;
        w8a = make_float4(W_out[(r0 + 0) * 64 + col8], W_out[(r0 + 1) * 64 + col8],
                          W_out[(r0 + 2) * 64 + col8], W_out[(r0 + 3) * 64 + col8]);
    }
    const float w8b = W_out[(256 + ch8) * 64 + col8];
    const float bo  = (t < 16) ? b_out[rank * 16 + t] : 0.f;

    // ---- init ----
    {
        float4 iv = make_float4(0.01f, 0.01f, 0.01f, 0.01f);
#pragma unroll
        for (int i = 0; i < 8; ++i) mem4[i * 1024 + t] = iv;
        if (t < 512) { float w0 = ((rank & 1) == 0 && t == 0) ? 1.f : 0.f; s->wr[t] = w0; s->ww[t] = w0; }
        if (t < 768) s->vh[t] = make_float2(0.f, 0.f);
        if (t < 256) s->h2c[t] = make_float2(0.f, 0.f);
        if (t < 128) ((float*)s->c)[t] = 0.f;
        if (t < 64)  { s->rvec2[t] = make_float2(0.f, 0.f); s->h2own[t] = make_float2(0.f, 0.f);
                       s->e[t] = 0.f; s->a[t] = 0.f; }   // step-0 deferred update = identity
        if (t < 64) {
            float2 xv = make_float2(x[(bgA << 6) * 64 + t], x[(bgB << 6) * 64 + t]);
            s->vh[t] = xv; s->vh[384 + t] = xv;
        }
        if (t == 0) {
            float hv = (rank & 1) ? 1.f : 0.f;
            s->wh_r[0] = hv; s->wh_w[0] = hv;
            s->wh_r[1] = 0.f; s->wh_w[1] = 0.f;
        }
    }
    cl.sync();

    float2 xpref = make_float2(0.f, 0.f);

    for (int step = 0; step < 64; ++step) {
        const int prv = step & 1, cur = prv ^ 1;

        // ---- gates GEMM, own 256 cols x 2 batches, packed ----
        {
            int qi = t & 63, qb = qi >> 4, qw = qi & 15;
            int col4 = qb * 64 + rank * 16 + qw;
            int ch = t >> 6;
            const ulonglong2* gw2 = (const ulonglong2*)g_W;
            const float2* vrow = s->vh + prv * 384;
            u64 aA01 = 0ull, aA23 = 0ull, aB01 = 0ull, aB23 = 0ull;
            int r0 = ch * 24;
#pragma unroll 8
            for (int rr = r0; rr < r0 + 24; ++rr) {
                ulonglong2 w2 = gw2[rr * 256 + col4];
                float2 vv = vrow[rr];
                u64 vA2 = pk2(vv.x, vv.x), vB2 = pk2(vv.y, vv.y);
                fma2(aA01, w2.x, vA2); fma2(aA23, w2.y, vA2);
                fma2(aB01, w2.x, vB2); fma2(aB23, w2.y, vB2);
            }
            ulonglong2 sa; sa.x = aA01; sa.y = aA23;
            ulonglong2 sb; sb.x = aB01; sb.y = aB23;
            partq[t] = sa;
            partq[1024 + t] = sb;
        }
        __syncthreads();
        if (t < 128) {
            int bat = t >> 6, qi = t & 63;
            int qb = qi >> 4, qw = qi & 15;
            int col4 = qb * 64 + rank * 16 + qw;
            ulonglong2 bb = ((const ulonglong2*)b_lstm)[col4];
            u64 a01 = bb.x, a23 = bb.y;
#pragma unroll
            for (int ch = 0; ch < 16; ++ch) {
                ulonglong2 pc = partq[bat * 1024 + ch * 64 + qi];
                a01 = add2(a01, pc.x); a23 = add2(a23, pc.y);
            }
            ulonglong2 g; g.x = a01; g.y = a23;
            ((ulonglong2*)s->gates[bat])[qi] = g;
        }
        __syncthreads();

        // ---- LSTM pointwise on own quarter; broadcast h; stash own pairs ----
        if (t < 128) {
            int bat = t >> 6, jl = t & 63;
            float ig = s->gates[bat][jl],       fg = s->gates[bat][64 + jl],
                  gg = s->gates[bat][128 + jl], og = s->gates[bat][192 + jl];
            float cc = sigmoidf_(fg) * s->c[bat][jl] + sigmoidf_(ig) * tanhf(gg);
            s->c[bat][jl] = cc;
            float hv = sigmoidf_(og) * tanhf(cc);
            int gj = rank * 64 + jl;
            ((float*)&s->h2own[jl])[bat] = hv;
#pragma unroll
            for (int i = 0; i < 4; ++i) {
                ((float*)&PP[i]->vh[128 + cur * 384 + gj])[bat] = hv;
                ((float*)&PP[i]->h2c[gj])[bat] = hv;
            }
        }
        __syncthreads();

        // ---- head PARTIAL GEMM from own h quarter (64 rows x 268 cols, packed) ----
        if (t < 536) {
            int half = t / 268, j = t - half * 268;
            const float* whp = W_head + (64 * rank + half * 32) * 268 + j;
            u64 acc = 0ull;
#pragma unroll 8
            for (int k = 0; k < 32; ++k) {
                float w = whp[k * 268];
                u64 hv = *(const u64*)(s->h2own + half * 32 + k);
                fma2(acc, hv, pk2(w, w));
            }
            part2[t] = up2(acc);
        }
        __syncthreads();
        if (t < 268) {
            float2 pa = part2[t], pb = part2[t + 268];
            float vx = pa.x + pb.x, vy = pa.y + pb.y;
            P0->ppart[rank][t] = vx; P1->ppart[rank][t] = vx;
            P2->ppart[rank][t] = vy; P3->ppart[rank][t] = vy;
        }
        CL_ARRIVE();   // S1 arrive
        // ---- S1 shadow: DEFERRED memory update (prev ww,e,a) + norm accumulation ----
        {
            int n4 = t & 127, mch = t >> 7;
            ulonglong2 ww2 = ((const ulonglong2*)s->ww)[n4];
            const u64 one2 = pk2(1.f, 1.f);
            u64 nn01 = 0ull, nn23 = 0ull;
#pragma unroll 4
            for (int mi = 0; mi < 8; ++mi) {
                int m = mch * 8 + mi;
                float em = s->e[m], am = s->a[m];
                u64 nem2 = pk2(-em, -em), am2 = pk2(am, am);
                ulonglong2 v2 = memq[m * 128 + n4];
                v2.x = fma2n(v2.x, fma2n(ww2.x, nem2, one2), mul2(ww2.x, am2));
                v2.y = fma2n(v2.y, fma2n(ww2.y, nem2, one2), mul2(ww2.y, am2));
                memq[m * 128 + n4] = v2;
                fma2(nn01, v2.x, v2.x); fma2(nn23, v2.y, v2.y);
            }
            ulonglong2 nnq; nnq.x = nn01; nnq.y = nn23;
            ((ulonglong2*)s->part)[1024 + mch * 128 + n4] = nnq;
        }
        CL_WAIT();     // S1: full h + head partials everywhere
        __syncthreads();   // order shadow writes intra-CTA

        // ---- post-S1: sum head partials (own batch) + reduce norms ----
        if (t < 268) {
            s->p[t] = s->ppart[0][t] + s->ppart[1][t] + s->ppart[2][t] + s->ppart[3][t]
                    + b_head[t];
        } else if (t >= 512) {
            int nl0 = t - 512;
            float nn = 0.f;
#pragma unroll
            for (int mch = 0; mch < 8; ++mch) nn += partf[4096 + mch * 512 + nl0];
            s->nnp[nl0] = nn;
        }
        __syncthreads();

        // ---- parse heads ----
        if (t < 64) s->krw[t].x = tanhf(s->p[t]);
        else if (t < 128) s->krw[t - 64].y = tanhf(s->p[70 + t - 64]);
        else if (t < 192) s->e[t - 128] = sigmoidf_(s->p[140 + (t - 128)]);
        else if (t < 256) s->a[t - 192] = s->p[204 + (t - 192)];
        else if (t == 256) {
            s->scal[0] = softplusf_(s->p[64]);
            s->scal[1] = sigmoidf_(s->p[65]);
            float a0 = s->p[66], a1 = s->p[67], a2 = s->p[68];
            float mx = fmaxf(a0, fmaxf(a1, a2));
            float e0 = expf(a0 - mx), e1 = expf(a1 - mx), e2 = expf(a2 - mx);
            float sm = e0 + e1 + e2;
            s->scal[2] = e0 / sm; s->scal[3] = e1 / sm; s->scal[4] = e2 / sm;
            s->scal[5] = 1.f + softplusf_(s->p[69]);
        } else if (t == 288) {
            s->scal[8] = softplusf_(s->p[134]);
            s->scal[9] = sigmoidf_(s->p[135]);
            float a0 = s->p[136], a1 = s->p[137], a2 = s->p[138];
            float mx = fmaxf(a0, fmaxf(a1, a2));
            float e0 = expf(a0 - mx), e1 = expf(a1 - mx), e2 = expf(a2 - mx);
            float sm = e0 + e1 + e2;
            s->scal[10] = e0 / sm; s->scal[11] = e1 / sm; s->scal[12] = e2 / sm;
            s->scal[13] = 1.f + softplusf_(s->p[139]);
        }
        __syncthreads();
        if (t < 32) {
            float kv = s->krw[t].x, kv2 = s->krw[t + 32].x;
            float v = kv * kv + kv2 * kv2;
#pragma unroll
            for (int o = 16; o; o >>= 1) v += __shfl_xor_sync(0xffffffffu, v, o);
            if (t == 0) s->scal[6] = sqrtf(v);
        } else if (t < 64) {
            int l = t - 32;
            float kv = s->krw[l].y, kv2 = s->krw[l + 32].y;
            float v = kv * kv + kv2 * kv2;
#pragma unroll
            for (int o = 16; o; o >>= 1) v += __shfl_xor_sync(0xffffffffu, v, o);
            if (l == 0) s->scal[7] = sqrtf(v);
        }
        __syncthreads();

        // ---- addressing dots over own 512 n-rows (updated mem), packed ----
        const int nl = t & 511, mh = t >> 9;
        {
            u64 drw = 0ull;
            int m0 = mh * 32;
#pragma unroll 8
            for (int m = m0; m < m0 + 32; ++m) {
                float v = s->mem[m * 512 + nl];
                u64 kv = *(const u64*)(s->krw + m);
                fma2(drw, kv, pk2(v, v));
            }
            float2 d = up2(drw);
            s->part[t] = make_float4(d.x, d.y, 0.f, 0.f);
        }
        __syncthreads();
        const bool lead = (t < 512);
        float qr = 0.f, qw = 0.f, er = 0.f, ew = 0.f;
        if (lead) {
            float4 p0 = s->part[t], p1 = s->part[t + 512];
            float dr = p0.x + p1.x, dw = p0.y + p1.y;
            float nrm = sqrtf(s->nnp[nl]);
            qr = s->scal[0] * (dr / (s->scal[6] * nrm + EPS));
            qw = s->scal[8] * (dw / (s->scal[7] * nrm + EPS));
            if (nl == 0)   { pp->qhalo[0] = qr; pp->qhalo[2] = qw; }
            if (nl == 511) { pp->qhalo[1] = qr; pp->qhalo[3] = qw; }
            er = expf(qr);
            ew = expf(qw);
        }
        float2 lsum = blockReduceSum2(make_float2(er, ew), s->red);
        if (t == 0) { pp->xch[0] = lsum.x; pp->xch[1] = lsum.y; }
        CL_ARRIVE();   // S3 arrive
        // ---- S3 shadow: out-GEMM h-part ----
        {
            const float* hb = (const float*)s->h2c;
            int r0 = ch8 * 4;
            u64 acc = 0ull;
            u64 h0 = *(const u64*)(hb + 2 * (r0 + 0));
            u64 h1 = *(const u64*)(hb + 2 * (r0 + 1));
            u64 h2 = *(const u64*)(hb + 2 * (r0 + 2));
            u64 h3 = *(const u64*)(hb + 2 * (r0 + 3));
            fma2(acc, h0, pk2(w8a.x, w8a.x));
            fma2(acc, h1, pk2(w8a.y, w8a.y));
            fma2(acc, h2, pk2(w8a.z, w8a.z));
            fma2(acc, h3, pk2(w8a.w, w8a.w));
            part2[3072 + t] = up2(acc);
        }
        CL_WAIT();     // S3: pair softmax sums + boundary q
        const float gsr = lsum.x + s->xch[0];
        const float gsw = lsum.y + s->xch[1];
        const float g_r = s->scal[1], g_w = s->scal[9];
        if (lead) {
            float wgr = g_r * (er / gsr) + (1.f - g_r) * s->wr[nl];
            float wgw = g_w * (ew / gsw) + (1.f - g_w) * s->ww[nl];
            s->t1[nl] = wgr;
            s->t2[nl] = wgw;
        }
        __syncthreads();
        float wpr = 0.f, wpw = 0.f;
        if (lead) {
            float t1p = (nl == 511) ? (g_r * (expf(s->qhalo[0]) / gsr) + (1.f - g_r) * s->wh_r[0]) : s->t1[nl + 1];
            float t1m = (nl == 0)   ? (g_r * (expf(s->qhalo[1]) / gsr) + (1.f - g_r) * s->wh_r[1]) : s->t1[nl - 1];
            float t2p = (nl == 511) ? (g_w * (expf(s->qhalo[2]) / gsw) + (1.f - g_w) * s->wh_w[0]) : s->t2[nl + 1];
            float t2m = (nl == 0)   ? (g_w * (expf(s->qhalo[3]) / gsw) + (1.f - g_w) * s->wh_w[1]) : s->t2[nl - 1];
            float wsr = s->scal[2]  * t1p + s->scal[3]  * s->t1[nl] + s->scal[4]  * t1m;
            float wsw = s->scal[10] * t2p + s->scal[11] * s->t2[nl] + s->scal[12] * t2m;
            wpr = (wsr > 0.f) ? expf(s->scal[5]  * logf(wsr)) : 0.f;
            wpw = (wsw > 0.f) ? expf(s->scal[13] * logf(wsw)) : 0.f;
            s->wr[nl] = wpr;      // UNNORMALIZED; normalized post-S45
            s->ww[nl] = wpw;
            if (nl == 0)   { pp->whp_r[0] = wpr; pp->whp_w[0] = wpw; }
            if (nl == 511) { pp->whp_r[1] = wpr; pp->whp_w[1] = wpw; }
        }
        float2 lsp = blockReduceSum2(make_float2(wpr, wpw), s->red);  // bar publishes s->wr

        // ---- read pass with UNNORMALIZED wr over current mem ----
        {
            int n4 = t & 127, mch = t >> 7, wid = t >> 5;
            ulonglong2 wr2 = ((const ulonglong2*)s->wr)[n4];
#pragma unroll 4
            for (int mi = 0; mi < 8; ++mi) {
                int m = mch * 8 + mi;
                ulonglong2 v2 = memq[m * 128 + n4];
                u64 rp2 = 0ull;
                fma2(rp2, wr2.x, v2.x); fma2(rp2, wr2.y, v2.y);
                float2 rr = up2(rp2);
                float rp = rr.x + rr.y;
#pragma unroll
                for (int o = 16; o; o >>= 1) rp += __shfl_xor_sync(0xffffffffu, rp, o);
                if ((t & 31) == 0) partf[4096 + wid * 8 + mi] = rp;
            }
        }
        __syncthreads();
        if (t < 64) {
            int grp = t >> 3, mi = t & 7;
            float v = partf[4096 + (grp * 4 + 0) * 8 + mi]
                    + partf[4096 + (grp * 4 + 1) * 8 + mi]
                    + partf[4096 + (grp * 4 + 2) * 8 + mi]
                    + partf[4096 + (grp * 4 + 3) * 8 + mi];
#pragma unroll
            for (int i = 0; i < 4; ++i) PP[i]->rrecv[rank][t] = v;
        }
        if (t == 0) {
#pragma unroll
            for (int i = 0; i < 4; ++i) PP[i]->zrecv[rank] = lsp;
        }
        CL_ARRIVE();   // S45 arrive
        if (t < 64) {
            int sn = (step < 63) ? step + 1 : 63;
            xpref = make_float2(x[((bgA << 6) + sn) * 64 + t],
                                x[((bgB << 6) + sn) * 64 + t]);
        }
        CL_WAIT();     // S45: sharpen sums + r partials + boundary wp everywhere

        // ---- post-S45: normalize, assemble r, stage next inputs ----
        {
            float2 z0 = s->zrecv[0], z1 = s->zrecv[1], z2 = s->zrecv[2], z3 = s->zrecv[3];
            float invZrA = 1.f / ((z0.x + z1.x) + EPS), invZwA = 1.f / ((z0.y + z1.y) + EPS);
            float invZrB = 1.f / ((z2.x + z3.x) + EPS), invZwB = 1.f / ((z2.y + z3.y) + EPS);
            float invZr = (rank < 2) ? invZrA : invZrB;
            float invZw = (rank < 2) ? invZwA : invZwB;
            if (lead) { s->wr[nl] *= invZr; s->ww[nl] *= invZw; }
            if (t == 0) {
                s->wh_r[0] = s->whp_r[0] * invZr; s->wh_r[1] = s->whp_r[1] * invZr;
                s->wh_w[0] = s->whp_w[0] * invZw; s->wh_w[1] = s->whp_w[1] * invZw;
            }
            if (t < 64) {
                float2 rv = make_float2((s->rrecv[0][t] + s->rrecv[1][t]) * invZrA,
                                        (s->rrecv[2][t] + s->rrecv[3][t]) * invZrB);
                s->rvec2[t] = rv;
                s->vh[64 + t] = rv;   s->vh[448 + t] = rv;
                s->vh[t] = xpref;     s->vh[384 + t] = xpref;
            }
        }
        __syncthreads();

        // ---- out: add r-part, reduce, write ----
        {
            float2 rv = s->rvec2[ch8];
            float2 pv = part2[3072 + t];
            pv.x += rv.x * w8b; pv.y += rv.y * w8b;
            part2[3072 + t] = pv;
        }
        __syncthreads();
        if (t < 128) {
            int jc = t & 15, g = t >> 4;
            float2 acc = make_float2(0.f, 0.f);
#pragma unroll
            for (int k = 0; k < 8; ++k) {
                float2 pv = part2[3072 + (g * 8 + k) * 16 + jc];
                acc.x += pv.x; acc.y += pv.y;
            }
            part2[t] = acc;
        }
        __syncthreads();
        if (t < 16) {
            float2 acc = make_float2(bo, bo);
#pragma unroll
            for (int g = 0; g < 8; ++g) {
                float2 pv = part2[g * 16 + t];
                acc.x += pv.x; acc.y += pv.y;
            }
            int col = rank * 16 + t;
            out[((bgA << 6) + step) * 64 + col] = acc.x;
            out[((bgB << 6) + step) * 64 + col] = acc.y;
        }
        __syncthreads();
    }
}

extern "C" void kernel_launch(void* const* d_in, const int* in_sizes, int n_in,
                              void* d_out, int out_size) {
    const float* x      = (const float*)d_in[0];
    const float* Wx     = (const float*)d_in[1];
    const float* Wh     = (const float*)d_in[2];
    const float* b_lstm = (const float*)d_in[3];
    const float* W_head = (const float*)d_in[4];
    const float* b_head = (const float*)d_in[5];
    const float* W_out  = (const float*)d_in[6];
    const float* b_out  = (const float*)d_in[7];
    float* out = (float*)d_out;

    cudaMemcpyToSymbolAsync(g_W, Wx, 128 * 1024 * sizeof(float), 0,
                            cudaMemcpyDeviceToDevice, 0);
    cudaMemcpyToSymbolAsync(g_W, Wh, 256 * 1024 * sizeof(float),
                            128 * 1024 * sizeof(float), cudaMemcpyDeviceToDevice, 0);

    size_t smem = sizeof(SMem);
    cudaFuncSetAttribute(ntm_kernel, cudaFuncAttributeMaxDynamicSharedMemorySize, (int)smem);
    ntm_kernel<<<128, 1024, smem>>>(x, b_lstm, W_head, b_head, W_out, b_out, out);
}